// round 2
// baseline (speedup 1.0000x reference)
#include <cuda_runtime.h>
#include <math.h>

#define BB 2
#define LL 2048
#define EE 1024
#define HH 16
#define HD 64
#define MROWS (BB*LL)

// Scratch (device globals; no runtime allocation allowed)
__device__ float g_q[BB*HH*LL*HD];    // scaled + rope'd, [b,h,l,hd]
__device__ float g_k[BB*HH*LL*HD];    // rope'd, [b,h,l,hd]
__device__ float g_v[BB*HH*LL*HD];    // [b,h,l,hd]
__device__ float g_att[BB*LL*EE];     // attention out, [b,l,e] row-major
__device__ float g_cos[LL*(HD/2)];
__device__ float g_sin[LL*(HD/2)];

__global__ void rope_init_kernel() {
    int idx = blockIdx.x * blockDim.x + threadIdx.x;
    if (idx >= LL * (HD/2)) return;
    int l = idx >> 5;
    int i = idx & 31;
    // inv_freq = theta^(-(2i)/dim)
    float inv = (float)pow(10000.0, -(double)(2 * i) / (double)HD);
    float f = (float)l * inv;
    g_cos[idx] = cosf(f);
    g_sin[idx] = sinf(f);
}

// C[m,n] = sum_k X[m,k]*W[n,k] + bias[n]
// MODE 0: plain -> outp[m*EE+n] (X = g_att)
// MODE 1: rope + 0.125 scale -> g_q[b,h,l,hd]
// MODE 2: rope -> g_k
// MODE 3: plain -> g_v
template<int MODE>
__global__ __launch_bounds__(256) void gemm_kernel(const float* __restrict__ Xp,
                                                   const float* __restrict__ Wp,
                                                   const float* __restrict__ bias,
                                                   float* __restrict__ outp) {
    __shared__ float Xs[8][128];
    __shared__ float Ws[8][128];

    const float* X = (MODE == 0) ? (const float*)g_att : Xp;

    const int tid = threadIdx.x;
    const int m0 = blockIdx.y * 128;
    const int n0 = blockIdx.x * 128;

    const int lr = tid >> 1;           // 0..127
    const int lc = (tid & 1) * 4;      // 0 or 4

    const float* Xg = X  + (size_t)(m0 + lr) * EE + lc;
    const float* Wg = Wp + (size_t)(n0 + lr) * EE + lc;

    const int ty = tid >> 4;           // 0..15: rows ty*8..+7
    const int tx = tid & 15;           // 0..15: cols tx*8..+7

    float acc[8][8];
    #pragma unroll
    for (int i = 0; i < 8; i++)
        #pragma unroll
        for (int j = 0; j < 8; j++) acc[i][j] = 0.f;

    float4 xv = *(const float4*)(Xg);
    float4 wv = *(const float4*)(Wg);

    for (int k0 = 0; k0 < EE; k0 += 8) {
        __syncthreads();
        Xs[lc+0][lr] = xv.x; Xs[lc+1][lr] = xv.y; Xs[lc+2][lr] = xv.z; Xs[lc+3][lr] = xv.w;
        Ws[lc+0][lr] = wv.x; Ws[lc+1][lr] = wv.y; Ws[lc+2][lr] = wv.z; Ws[lc+3][lr] = wv.w;
        __syncthreads();
        if (k0 + 8 < EE) {
            xv = *(const float4*)(Xg + k0 + 8);
            wv = *(const float4*)(Wg + k0 + 8);
        }
        #pragma unroll
        for (int kk = 0; kk < 8; kk++) {
            float a[8], bfr[8];
            #pragma unroll
            for (int i = 0; i < 8; i++) a[i] = Xs[kk][ty*8 + i];
            #pragma unroll
            for (int j = 0; j < 8; j++) bfr[j] = Ws[kk][tx*8 + j];
            #pragma unroll
            for (int i = 0; i < 8; i++)
                #pragma unroll
                for (int j = 0; j < 8; j++)
                    acc[i][j] += a[i] * bfr[j];
        }
    }

    float bj[8];
    #pragma unroll
    for (int j = 0; j < 8; j++) bj[j] = bias[n0 + tx*8 + j];

    #pragma unroll
    for (int i = 0; i < 8; i++) {
        const int m = m0 + ty*8 + i;
        const int l = m & (LL - 1);
        const int bi = m >> 11;
        if (MODE == 0) {
            #pragma unroll
            for (int j = 0; j < 8; j++) {
                int n = n0 + tx*8 + j;
                outp[(size_t)m * EE + n] = acc[i][j] + bj[j];
            }
        } else if (MODE == 3) {
            #pragma unroll
            for (int j = 0; j < 8; j++) {
                int n = n0 + tx*8 + j;
                int h = n >> 6, hd = n & 63;
                g_v[((size_t)(bi*HH + h)*LL + l)*HD + hd] = acc[i][j] + bj[j];
            }
        } else {
            #pragma unroll
            for (int j = 0; j < 8; j += 2) {
                int n = n0 + tx*8 + j;
                int h = n >> 6, hd = n & 63;
                float v0 = acc[i][j]   + bj[j];
                float v1 = acc[i][j+1] + bj[j+1];
                float c = g_cos[l*32 + (hd >> 1)];
                float s = g_sin[l*32 + (hd >> 1)];
                float r0 = v0 * c - v1 * s;
                float r1 = v1 * c + v0 * s;
                if (MODE == 1) { r0 *= 0.125f; r1 *= 0.125f; }  // 1/sqrt(64) folded into q
                float* dst = (MODE == 1) ? g_q : g_k;
                size_t idx = ((size_t)(bi*HH + h)*LL + l)*HD + hd;
                dst[idx]   = r0;
                dst[idx+1] = r1;
            }
        }
    }
}

// Flash attention, BQ=64 query rows per block, BKV=64 keys per tile.
// 128 threads; microtile 4 rows x 8 cols (cols strided by 8).
__global__ __launch_bounds__(128) void attn_kernel() {
    extern __shared__ float sm[];
    float* qs = sm;                 // [64][65]
    float* ks = sm + 64*65;         // [64][65]
    float* vs = sm + 2*64*65;       // [64][65]
    float* ss = sm + 3*64*65;       // [64][65]

    const int tid = threadIdx.x;
    const int bh = blockIdx.x;               // 0..B*H-1
    const int q0 = blockIdx.y * 64;
    const int bi = bh >> 4;
    const int h  = bh & 15;

    const float* qb = g_q + (size_t)bh * LL * HD;
    const float* kb = g_k + (size_t)bh * LL * HD;
    const float* vb = g_v + (size_t)bh * LL * HD;

    const int rg = tid >> 3;   // 0..15 -> rows rg*4+i
    const int cg = tid & 7;    // 0..7  -> cols cg+8*j

    // Load q tile (64x64) into smem
    #pragma unroll
    for (int it = 0; it < 8; it++) {
        int idx = tid + it * 128;
        int row = idx >> 4;
        int c4 = (idx & 15) << 2;
        float4 t = *(const float4*)(qb + (size_t)(q0 + row) * HD + c4);
        float* d = qs + row * 65 + c4;
        d[0] = t.x; d[1] = t.y; d[2] = t.z; d[3] = t.w;
    }

    float o[4][8];
    float m_i[4], l_i[4];
    #pragma unroll
    for (int i = 0; i < 4; i++) {
        m_i[i] = -1e30f; l_i[i] = 0.f;
        #pragma unroll
        for (int j = 0; j < 8; j++) o[i][j] = 0.f;
    }

    for (int kt = 0; kt < LL; kt += 64) {
        __syncthreads();   // protect ks/vs/ss from previous iteration's readers
        #pragma unroll
        for (int it = 0; it < 8; it++) {
            int idx = tid + it * 128;
            int row = idx >> 4;
            int c4 = (idx & 15) << 2;
            float4 t = *(const float4*)(kb + (size_t)(kt + row) * HD + c4);
            float* d = ks + row * 65 + c4;
            d[0] = t.x; d[1] = t.y; d[2] = t.z; d[3] = t.w;
            float4 u = *(const float4*)(vb + (size_t)(kt + row) * HD + c4);
            float* e = vs + row * 65 + c4;
            e[0] = u.x; e[1] = u.y; e[2] = u.z; e[3] = u.w;
        }
        __syncthreads();

        // S = q @ k^T  (scale already folded into q)
        float s[4][8];
        #pragma unroll
        for (int i = 0; i < 4; i++)
            #pragma unroll
            for (int j = 0; j < 8; j++) s[i][j] = 0.f;

        #pragma unroll 8
        for (int k = 0; k < 64; k++) {
            float a[4], bfr[8];
            #pragma unroll
            for (int i = 0; i < 4; i++) a[i] = qs[(rg*4 + i)*65 + k];
            #pragma unroll
            for (int j = 0; j < 8; j++) bfr[j] = ks[(cg + 8*j)*65 + k];
            #pragma unroll
            for (int i = 0; i < 4; i++)
                #pragma unroll
                for (int j = 0; j < 8; j++)
                    s[i][j] += a[i] * bfr[j];
        }

        // Online softmax update (rows split over 8 lanes -> shuffle reduce)
        #pragma unroll
        for (int i = 0; i < 4; i++) {
            float mx = s[i][0];
            #pragma unroll
            for (int j = 1; j < 8; j++) mx = fmaxf(mx, s[i][j]);
            mx = fmaxf(mx, __shfl_xor_sync(0xffffffffu, mx, 1));
            mx = fmaxf(mx, __shfl_xor_sync(0xffffffffu, mx, 2));
            mx = fmaxf(mx, __shfl_xor_sync(0xffffffffu, mx, 4));
            float mnew = fmaxf(m_i[i], mx);
            float alpha = __expf(m_i[i] - mnew);
            float rsum = 0.f;
            #pragma unroll
            for (int j = 0; j < 8; j++) {
                s[i][j] = __expf(s[i][j] - mnew);
                rsum += s[i][j];
            }
            rsum += __shfl_xor_sync(0xffffffffu, rsum, 1);
            rsum += __shfl_xor_sync(0xffffffffu, rsum, 2);
            rsum += __shfl_xor_sync(0xffffffffu, rsum, 4);
            l_i[i] = l_i[i] * alpha + rsum;
            m_i[i] = mnew;
            #pragma unroll
            for (int j = 0; j < 8; j++) {
                o[i][j] *= alpha;
                ss[(rg*4 + i)*65 + cg + 8*j] = s[i][j];
            }
        }
        __syncthreads();

        // O += P @ V
        #pragma unroll 8
        for (int k = 0; k < 64; k++) {
            float a[4], bfr[8];
            #pragma unroll
            for (int i = 0; i < 4; i++) a[i] = ss[(rg*4 + i)*65 + k];
            #pragma unroll
            for (int j = 0; j < 8; j++) bfr[j] = vs[k*65 + cg + 8*j];
            #pragma unroll
            for (int i = 0; i < 4; i++)
                #pragma unroll
                for (int j = 0; j < 8; j++)
                    o[i][j] += a[i] * bfr[j];
        }
    }

    // Write out: [b, l, e] with e = h*64 + col
    #pragma unroll
    for (int i = 0; i < 4; i++) {
        float inv = 1.f / l_i[i];
        int r = q0 + rg*4 + i;
        float* dst = g_att + ((size_t)(bi * LL + r)) * EE + h * HD;
        #pragma unroll
        for (int j = 0; j < 8; j++)
            dst[cg + 8*j] = o[i][j] * inv;
    }
}

extern "C" void kernel_launch(void* const* d_in, const int* in_sizes, int n_in,
                              void* d_out, int out_size) {
    const float* x  = (const float*)d_in[0];
    const float* Wq = (const float*)d_in[1];
    const float* bq = (const float*)d_in[2];
    const float* Wk = (const float*)d_in[3];
    const float* bk = (const float*)d_in[4];
    const float* Wv = (const float*)d_in[5];
    const float* bv = (const float*)d_in[6];
    const float* Wo = (const float*)d_in[7];
    const float* bo = (const float*)d_in[8];
    float* out = (float*)d_out;

    rope_init_kernel<<<(LL*32 + 255) / 256, 256>>>();

    dim3 gg(EE / 128, MROWS / 128);
    gemm_kernel<1><<<gg, 256>>>(x, Wq, bq, nullptr);
    gemm_kernel<2><<<gg, 256>>>(x, Wk, bk, nullptr);
    gemm_kernel<3><<<gg, 256>>>(x, Wv, bv, nullptr);

    const int attn_smem = 4 * 64 * 65 * (int)sizeof(float);  // 66560 B
    cudaFuncSetAttribute(attn_kernel, cudaFuncAttributeMaxDynamicSharedMemorySize, attn_smem);
    attn_kernel<<<dim3(BB*HH, LL/64), 128, attn_smem>>>();

    gemm_kernel<0><<<gg, 256>>>(nullptr, Wo, bo, out);
}

// round 5
// speedup vs baseline: 1.3807x; 1.3807x over previous
#include <cuda_runtime.h>
#include <cuda_bf16.h>
#include <math.h>
#include <stdint.h>

#define BB 2
#define LL 2048
#define EE 1024
#define HH 16
#define HD 64
#define MROWS (BB*LL)

// Scratch (device globals; no runtime allocation allowed)
__device__ float g_q[MROWS*EE];       // [b*l, e] rope'd+scaled q
__device__ float g_k[MROWS*EE];       // [b*l, e] rope'd k
__device__ float g_v[MROWS*EE];       // [b*l, e]
__device__ float g_att[MROWS*EE];     // attention out, [b*l, e]
__device__ float g_cos[LL*(HD/2)];
__device__ float g_sin[LL*(HD/2)];
__device__ __nv_bfloat16 g_xhi[MROWS*EE];
__device__ __nv_bfloat16 g_xlo[MROWS*EE];
__device__ __nv_bfloat16 g_whi[EE*EE];
__device__ __nv_bfloat16 g_wlo[EE*EE];

__device__ __forceinline__ uint32_t smem_u32(const void* p) {
    uint32_t a;
    asm("{ .reg .u64 t; cvta.to.shared.u64 t, %1; cvt.u32.u64 %0, t; }" : "=r"(a) : "l"(p));
    return a;
}

__device__ __forceinline__ void ldsm4(uint32_t& r0, uint32_t& r1, uint32_t& r2, uint32_t& r3,
                                      uint32_t addr) {
    asm volatile("ldmatrix.sync.aligned.m8n8.x4.shared.b16 {%0,%1,%2,%3}, [%4];"
                 : "=r"(r0), "=r"(r1), "=r"(r2), "=r"(r3) : "r"(addr));
}

__device__ __forceinline__ void mma_bf16(float& d0, float& d1, float& d2, float& d3,
                                         uint32_t a0, uint32_t a1, uint32_t a2, uint32_t a3,
                                         uint32_t b0, uint32_t b1) {
    asm volatile(
        "mma.sync.aligned.m16n8k16.row.col.f32.bf16.bf16.f32 "
        "{%0,%1,%2,%3}, {%4,%5,%6,%7}, {%8,%9}, {%0,%1,%2,%3};"
        : "+f"(d0), "+f"(d1), "+f"(d2), "+f"(d3)
        : "r"(a0), "r"(a1), "r"(a2), "r"(a3), "r"(b0), "r"(b1));
}

// ---------------- init kernels ----------------
__global__ void rope_init_kernel() {
    int idx = blockIdx.x * blockDim.x + threadIdx.x;
    if (idx >= LL * (HD/2)) return;
    int l = idx >> 5;
    int i = idx & 31;
    float inv = (float)pow(10000.0, -(double)(2 * i) / (double)HD);
    float f = (float)l * inv;
    g_cos[idx] = cosf(f);
    g_sin[idx] = sinf(f);
}

// fp32 -> bf16 hi/lo split.  SRC 0: arg `in`; SRC 1: g_att.  DST 0: x; DST 1: w.
template<int SRC, int DST>
__global__ void split_kernel(const float* __restrict__ in, int n4) {
    int i = blockIdx.x * blockDim.x + threadIdx.x;
    if (i >= n4) return;
    const float* src = SRC ? (const float*)g_att : in;
    __nv_bfloat16* hi = DST ? g_whi : g_xhi;
    __nv_bfloat16* lo = DST ? g_wlo : g_xlo;
    float4 vv = ((const float4*)src)[i];
    float f[4] = {vv.x, vv.y, vv.z, vv.w};
    ushort4 ph, pl;
    unsigned short* hp = (unsigned short*)&ph;
    unsigned short* lp = (unsigned short*)&pl;
    #pragma unroll
    for (int j = 0; j < 4; j++) {
        __nv_bfloat16 h = __float2bfloat16(f[j]);
        __nv_bfloat16 l = __float2bfloat16(f[j] - __bfloat162float(h));
        hp[j] = __bfloat16_as_ushort(h);
        lp[j] = __bfloat16_as_ushort(l);
    }
    ((ushort4*)hi)[i] = ph;
    ((ushort4*)lo)[i] = pl;
}

// ---------------- HMMA GEMM ----------------
// C[m,n] = sum_k X[m,k]*W[n,k] + bias[n], bf16-split 3-term mma.sync, fp32 accum.
// MODE 0: -> outp   MODE 1: rope+0.125 -> g_q   MODE 2: rope -> g_k   MODE 3: -> g_v
// Block tile 128x128x32, 8 warps (warp tile 32x64).
#define LDSTR 40   // smem row stride in halves (32 data + 8 pad)

template<int MODE>
__global__ __launch_bounds__(256, 1) void gemm_mma(const float* __restrict__ bias,
                                                   float* __restrict__ outp) {
    __shared__ __nv_bfloat16 sAh[128*LDSTR];
    __shared__ __nv_bfloat16 sAl[128*LDSTR];
    __shared__ __nv_bfloat16 sBh[128*LDSTR];
    __shared__ __nv_bfloat16 sBl[128*LDSTR];
    __shared__ float bs[128];

    const int tid = threadIdx.x;
    const int wid = tid >> 5;
    const int lid = tid & 31;
    const int n0 = blockIdx.x * 128;
    const int m0 = blockIdx.y * 128;
    const int wm = (wid & 3) * 32;     // warp m offset in tile
    const int wn = (wid >> 2) * 64;    // warp n offset in tile

    if (tid < 128) bs[tid] = bias[n0 + tid];

    // copy indices: 512 uint4 segs per tile, 2 per thread
    const int row_a = tid >> 2;             // idx = tid      -> row, seg
    const int seg_a = tid & 3;
    const int row_b = (tid + 256) >> 2;     // idx = tid+256
    const int seg_b = (tid + 256) & 3;

    const __nv_bfloat16* Ahi = g_xhi + (size_t)m0 * EE;
    const __nv_bfloat16* Alo = g_xlo + (size_t)m0 * EE;
    const __nv_bfloat16* Bhi = g_whi + (size_t)n0 * EE;
    const __nv_bfloat16* Blo = g_wlo + (size_t)n0 * EE;

    // ldmatrix lane addressing (bytes)
    const uint32_t sbAh = smem_u32(sAh), sbAl = smem_u32(sAl);
    const uint32_t sbBh = smem_u32(sBh), sbBl = smem_u32(sBl);
    const int a_row = wm + (lid & 15);
    const int a_koff = (lid >> 4) * 8;                    // halves
    const int b_row = wn + (lid & 7) + ((lid >> 3) & 1) * 8;
    const int b_koff = (lid >> 4) * 8;

    float acc[2][8][4];
    #pragma unroll
    for (int i = 0; i < 2; i++)
        #pragma unroll
        for (int j = 0; j < 8; j++)
            #pragma unroll
            for (int r = 0; r < 4; r++) acc[i][j][r] = 0.f;

    uint4 pAh0, pAh1, pAl0, pAl1, pBh0, pBh1, pBl0, pBl1;
    {
        const size_t ga0 = (size_t)row_a * EE + seg_a * 8;
        const size_t ga1 = (size_t)row_b * EE + seg_b * 8;
        pAh0 = *(const uint4*)(Ahi + ga0); pAh1 = *(const uint4*)(Ahi + ga1);
        pAl0 = *(const uint4*)(Alo + ga0); pAl1 = *(const uint4*)(Alo + ga1);
        pBh0 = *(const uint4*)(Bhi + ga0); pBh1 = *(const uint4*)(Bhi + ga1);
        pBl0 = *(const uint4*)(Blo + ga0); pBl1 = *(const uint4*)(Blo + ga1);
    }

    for (int kc = 0; kc < EE/32; kc++) {
        __syncthreads();
        {
            const int so0 = row_a * LDSTR + seg_a * 8;
            const int so1 = row_b * LDSTR + seg_b * 8;
            *(uint4*)(sAh + so0) = pAh0; *(uint4*)(sAh + so1) = pAh1;
            *(uint4*)(sAl + so0) = pAl0; *(uint4*)(sAl + so1) = pAl1;
            *(uint4*)(sBh + so0) = pBh0; *(uint4*)(sBh + so1) = pBh1;
            *(uint4*)(sBl + so0) = pBl0; *(uint4*)(sBl + so1) = pBl1;
        }
        __syncthreads();
        if (kc + 1 < EE/32) {
            const int k1 = (kc + 1) * 32;
            const size_t ga0 = (size_t)row_a * EE + k1 + seg_a * 8;
            const size_t ga1 = (size_t)row_b * EE + k1 + seg_b * 8;
            pAh0 = *(const uint4*)(Ahi + ga0); pAh1 = *(const uint4*)(Ahi + ga1);
            pAl0 = *(const uint4*)(Alo + ga0); pAl1 = *(const uint4*)(Alo + ga1);
            pBh0 = *(const uint4*)(Bhi + ga0); pBh1 = *(const uint4*)(Bhi + ga1);
            pBl0 = *(const uint4*)(Blo + ga0); pBl1 = *(const uint4*)(Blo + ga1);
        }

        #pragma unroll
        for (int kk = 0; kk < 32; kk += 16) {
            uint32_t ah[2][4], al[2][4];
            #pragma unroll
            for (int mt = 0; mt < 2; mt++) {
                const uint32_t ao = ((a_row + mt*16) * LDSTR + kk + a_koff) * 2;
                ldsm4(ah[mt][0], ah[mt][1], ah[mt][2], ah[mt][3], sbAh + ao);
                ldsm4(al[mt][0], al[mt][1], al[mt][2], al[mt][3], sbAl + ao);
            }
            uint32_t bh[4][4], bl[4][4];
            #pragma unroll
            for (int nt = 0; nt < 4; nt++) {
                const uint32_t bo = ((b_row + nt*16) * LDSTR + kk + b_koff) * 2;
                ldsm4(bh[nt][0], bh[nt][1], bh[nt][2], bh[nt][3], sbBh + bo);
                ldsm4(bl[nt][0], bl[nt][1], bl[nt][2], bl[nt][3], sbBl + bo);
            }
            #pragma unroll
            for (int mt = 0; mt < 2; mt++)
                #pragma unroll
                for (int nt = 0; nt < 4; nt++) {
                    float* d0 = acc[mt][nt*2];
                    float* d1 = acc[mt][nt*2 + 1];
                    // hi * hi
                    mma_bf16(d0[0], d0[1], d0[2], d0[3],
                             ah[mt][0], ah[mt][1], ah[mt][2], ah[mt][3],
                             bh[nt][0], bh[nt][2]);
                    mma_bf16(d1[0], d1[1], d1[2], d1[3],
                             ah[mt][0], ah[mt][1], ah[mt][2], ah[mt][3],
                             bh[nt][1], bh[nt][3]);
                    // lo * hi
                    mma_bf16(d0[0], d0[1], d0[2], d0[3],
                             al[mt][0], al[mt][1], al[mt][2], al[mt][3],
                             bh[nt][0], bh[nt][2]);
                    mma_bf16(d1[0], d1[1], d1[2], d1[3],
                             al[mt][0], al[mt][1], al[mt][2], al[mt][3],
                             bh[nt][1], bh[nt][3]);
                    // hi * lo
                    mma_bf16(d0[0], d0[1], d0[2], d0[3],
                             ah[mt][0], ah[mt][1], ah[mt][2], ah[mt][3],
                             bl[nt][0], bl[nt][2]);
                    mma_bf16(d1[0], d1[1], d1[2], d1[3],
                             ah[mt][0], ah[mt][1], ah[mt][2], ah[mt][3],
                             bl[nt][1], bl[nt][3]);
                }
        }
    }

    // epilogue: bias (+ rope/scale) + store
    const int g = lid >> 2;
    const int tig = lid & 3;
    float* base = (MODE == 0) ? outp : (MODE == 3) ? g_v : (MODE == 1) ? g_q : g_k;

    #pragma unroll
    for (int mt = 0; mt < 2; mt++) {
        const int r0 = m0 + wm + mt*16 + g;
        const int r1 = r0 + 8;
        const int l0 = r0 & (LL - 1);
        const int l1 = r1 & (LL - 1);
        #pragma unroll
        for (int nt8 = 0; nt8 < 8; nt8++) {
            const int cl = wn + nt8*8 + tig*2;   // col within tile (even)
            const int c  = n0 + cl;
            float v00 = acc[mt][nt8][0] + bs[cl];
            float v01 = acc[mt][nt8][1] + bs[cl+1];
            float v10 = acc[mt][nt8][2] + bs[cl];
            float v11 = acc[mt][nt8][3] + bs[cl+1];
            if (MODE == 1 || MODE == 2) {
                const int p = (c & 63) >> 1;
                float c0 = g_cos[l0*32 + p], s0 = g_sin[l0*32 + p];
                float c1 = g_cos[l1*32 + p], s1 = g_sin[l1*32 + p];
                float t00 = v00 * c0 - v01 * s0;
                float t01 = v01 * c0 + v00 * s0;
                float t10 = v10 * c1 - v11 * s1;
                float t11 = v11 * c1 + v10 * s1;
                if (MODE == 1) { t00 *= 0.125f; t01 *= 0.125f; t10 *= 0.125f; t11 *= 0.125f; }
                v00 = t00; v01 = t01; v10 = t10; v11 = t11;
            }
            *(float2*)(base + (size_t)r0 * EE + c) = make_float2(v00, v01);
            *(float2*)(base + (size_t)r1 * EE + c) = make_float2(v10, v11);
        }
    }
}

// ---------------- flash attention (SIMT, q/k/v in [b*l, e] layout) ----------------
__global__ __launch_bounds__(128) void attn_kernel() {
    extern __shared__ float sm[];
    float* qs = sm;                 // [64][65]
    float* ks = sm + 64*65;
    float* vs = sm + 2*64*65;
    float* ss = sm + 3*64*65;

    const int tid = threadIdx.x;
    const int bh = blockIdx.x;
    const int q0 = blockIdx.y * 64;
    const int bi = bh >> 4;
    const int h  = bh & 15;

    const size_t base = (size_t)bi * LL * EE + h * HD;
    const float* qb = g_q + base;
    const float* kb = g_k + base;
    const float* vb = g_v + base;

    const int rg = tid >> 3;
    const int cg = tid & 7;

    #pragma unroll
    for (int it = 0; it < 8; it++) {
        int idx = tid + it * 128;
        int row = idx >> 4;
        int c4 = (idx & 15) << 2;
        float4 t = *(const float4*)(qb + (size_t)(q0 + row) * EE + c4);
        float* d = qs + row * 65 + c4;
        d[0] = t.x; d[1] = t.y; d[2] = t.z; d[3] = t.w;
    }

    float o[4][8];
    float m_i[4], l_i[4];
    #pragma unroll
    for (int i = 0; i < 4; i++) {
        m_i[i] = -1e30f; l_i[i] = 0.f;
        #pragma unroll
        for (int j = 0; j < 8; j++) o[i][j] = 0.f;
    }

    for (int kt = 0; kt < LL; kt += 64) {
        __syncthreads();
        #pragma unroll
        for (int it = 0; it < 8; it++) {
            int idx = tid + it * 128;
            int row = idx >> 4;
            int c4 = (idx & 15) << 2;
            float4 t = *(const float4*)(kb + (size_t)(kt + row) * EE + c4);
            float* d = ks + row * 65 + c4;
            d[0] = t.x; d[1] = t.y; d[2] = t.z; d[3] = t.w;
            float4 u = *(const float4*)(vb + (size_t)(kt + row) * EE + c4);
            float* e = vs + row * 65 + c4;
            e[0] = u.x; e[1] = u.y; e[2] = u.z; e[3] = u.w;
        }
        __syncthreads();

        float s[4][8];
        #pragma unroll
        for (int i = 0; i < 4; i++)
            #pragma unroll
            for (int j = 0; j < 8; j++) s[i][j] = 0.f;

        #pragma unroll 8
        for (int k = 0; k < 64; k++) {
            float a[4], bfr[8];
            #pragma unroll
            for (int i = 0; i < 4; i++) a[i] = qs[(rg*4 + i)*65 + k];
            #pragma unroll
            for (int j = 0; j < 8; j++) bfr[j] = ks[(cg + 8*j)*65 + k];
            #pragma unroll
            for (int i = 0; i < 4; i++)
                #pragma unroll
                for (int j = 0; j < 8; j++)
                    s[i][j] += a[i] * bfr[j];
        }

        #pragma unroll
        for (int i = 0; i < 4; i++) {
            float mx = s[i][0];
            #pragma unroll
            for (int j = 1; j < 8; j++) mx = fmaxf(mx, s[i][j]);
            mx = fmaxf(mx, __shfl_xor_sync(0xffffffffu, mx, 1));
            mx = fmaxf(mx, __shfl_xor_sync(0xffffffffu, mx, 2));
            mx = fmaxf(mx, __shfl_xor_sync(0xffffffffu, mx, 4));
            float mnew = fmaxf(m_i[i], mx);
            float alpha = __expf(m_i[i] - mnew);
            float rsum = 0.f;
            #pragma unroll
            for (int j = 0; j < 8; j++) {
                s[i][j] = __expf(s[i][j] - mnew);
                rsum += s[i][j];
            }
            rsum += __shfl_xor_sync(0xffffffffu, rsum, 1);
            rsum += __shfl_xor_sync(0xffffffffu, rsum, 2);
            rsum += __shfl_xor_sync(0xffffffffu, rsum, 4);
            l_i[i] = l_i[i] * alpha + rsum;
            m_i[i] = mnew;
            #pragma unroll
            for (int j = 0; j < 8; j++) {
                o[i][j] *= alpha;
                ss[(rg*4 + i)*65 + cg + 8*j] = s[i][j];
            }
        }
        __syncthreads();

        #pragma unroll 8
        for (int k = 0; k < 64; k++) {
            float a[4], bfr[8];
            #pragma unroll
            for (int i = 0; i < 4; i++) a[i] = ss[(rg*4 + i)*65 + k];
            #pragma unroll
            for (int j = 0; j < 8; j++) bfr[j] = vs[k*65 + cg + 8*j];
            #pragma unroll
            for (int i = 0; i < 4; i++)
                #pragma unroll
                for (int j = 0; j < 8; j++)
                    o[i][j] += a[i] * bfr[j];
        }
    }

    #pragma unroll
    for (int i = 0; i < 4; i++) {
        float inv = 1.f / l_i[i];
        int r = q0 + rg*4 + i;
        float* dst = g_att + ((size_t)(bi * LL + r)) * EE + h * HD;
        #pragma unroll
        for (int j = 0; j < 8; j++)
            dst[cg + 8*j] = o[i][j] * inv;
    }
}

extern "C" void kernel_launch(void* const* d_in, const int* in_sizes, int n_in,
                              void* d_out, int out_size) {
    const float* x  = (const float*)d_in[0];
    const float* Wq = (const float*)d_in[1];
    const float* bq = (const float*)d_in[2];
    const float* Wk = (const float*)d_in[3];
    const float* bk = (const float*)d_in[4];
    const float* Wv = (const float*)d_in[5];
    const float* bv = (const float*)d_in[6];
    const float* Wo = (const float*)d_in[7];
    const float* bo = (const float*)d_in[8];
    float* out = (float*)d_out;

    rope_init_kernel<<<(LL*32 + 255) / 256, 256>>>();

    const int xn4 = MROWS * EE / 4;
    const int wn4 = EE * EE / 4;
    split_kernel<0,0><<<(xn4 + 255) / 256, 256>>>(x, xn4);

    dim3 gg(EE / 128, MROWS / 128);
    split_kernel<0,1><<<(wn4 + 255) / 256, 256>>>(Wq, wn4);
    gemm_mma<1><<<gg, 256>>>(bq, nullptr);
    split_kernel<0,1><<<(wn4 + 255) / 256, 256>>>(Wk, wn4);
    gemm_mma<2><<<gg, 256>>>(bk, nullptr);
    split_kernel<0,1><<<(wn4 + 255) / 256, 256>>>(Wv, wn4);
    gemm_mma<3><<<gg, 256>>>(bv, nullptr);

    const int attn_smem = 4 * 64 * 65 * (int)sizeof(float);
    cudaFuncSetAttribute(attn_kernel, cudaFuncAttributeMaxDynamicSharedMemorySize, attn_smem);
    attn_kernel<<<dim3(BB*HH, LL/64), 128, attn_smem>>>();

    split_kernel<1,0><<<(xn4 + 255) / 256, 256>>>(nullptr, xn4);   // g_att -> xhi/xlo
    split_kernel<0,1><<<(wn4 + 255) / 256, 256>>>(Wo, wn4);
    gemm_mma<0><<<gg, 256>>>(bo, out);
}

// round 10
// speedup vs baseline: 2.3193x; 1.6798x over previous
#include <cuda_runtime.h>
#include <cuda_bf16.h>
#include <math.h>
#include <stdint.h>

#define BB 2
#define LL 2048
#define EE 1024
#define HH 16
#define HD 64
#define MROWS (BB*LL)

// Scratch (device globals; no runtime allocation allowed)
__device__ float g_att[MROWS*EE];     // attention out, [b*l, e]
__device__ float g_cos[LL*(HD/2)];
__device__ float g_sin[LL*(HD/2)];
__device__ __nv_bfloat16 g_xhi[MROWS*EE];
__device__ __nv_bfloat16 g_xlo[MROWS*EE];
__device__ __nv_bfloat16 g_whi[EE*EE];
__device__ __nv_bfloat16 g_wlo[EE*EE];
// rope'd/scaled projections, bf16 hi/lo, [b*l, e]
__device__ __nv_bfloat16 g_qh[MROWS*EE];
__device__ __nv_bfloat16 g_ql[MROWS*EE];
__device__ __nv_bfloat16 g_kh[MROWS*EE];
__device__ __nv_bfloat16 g_kl[MROWS*EE];
__device__ __nv_bfloat16 g_vh[MROWS*EE];
__device__ __nv_bfloat16 g_vl[MROWS*EE];

__device__ __forceinline__ uint32_t smem_u32(const void* p) {
    uint32_t a;
    asm("{ .reg .u64 t; cvta.to.shared.u64 t, %1; cvt.u32.u64 %0, t; }" : "=r"(a) : "l"(p));
    return a;
}

__device__ __forceinline__ void ldsm4(uint32_t& r0, uint32_t& r1, uint32_t& r2, uint32_t& r3,
                                      uint32_t addr) {
    asm volatile("ldmatrix.sync.aligned.m8n8.x4.shared.b16 {%0,%1,%2,%3}, [%4];"
                 : "=r"(r0), "=r"(r1), "=r"(r2), "=r"(r3) : "r"(addr));
}
__device__ __forceinline__ void ldsm4t(uint32_t* r, uint32_t addr) {
    asm volatile("ldmatrix.sync.aligned.m8n8.x4.trans.shared.b16 {%0,%1,%2,%3}, [%4];"
                 : "=r"(r[0]), "=r"(r[1]), "=r"(r[2]), "=r"(r[3]) : "r"(addr));
}

__device__ __forceinline__ void mma_bf16(float& d0, float& d1, float& d2, float& d3,
                                         uint32_t a0, uint32_t a1, uint32_t a2, uint32_t a3,
                                         uint32_t b0, uint32_t b1) {
    asm volatile(
        "mma.sync.aligned.m16n8k16.row.col.f32.bf16.bf16.f32 "
        "{%0,%1,%2,%3}, {%4,%5,%6,%7}, {%8,%9}, {%0,%1,%2,%3};"
        : "+f"(d0), "+f"(d1), "+f"(d2), "+f"(d3)
        : "r"(a0), "r"(a1), "r"(a2), "r"(a3), "r"(b0), "r"(b1));
}

// pack (col c -> lo half, col c+1 -> hi half)
__device__ __forceinline__ uint32_t packbf(float a, float b) {
    uint32_t r;
    asm("cvt.rn.bf16x2.f32 %0, %1, %2;" : "=r"(r) : "f"(b), "f"(a));
    return r;
}
__device__ __forceinline__ float lof(uint32_t u) { return __int_as_float(u << 16); }
__device__ __forceinline__ float hif(uint32_t u) { return __int_as_float(u & 0xFFFF0000u); }

// fast 2^t on the FMA pipe (t <= 0 expected; clamped)
__device__ __forceinline__ float exp2p(float t) {
    t = fmaxf(t, -125.f);
    float kf = t + 12582912.f;        // round to nearest int (RN magic)
    float nf = kf - 12582912.f;
    float f = t - nf;                 // [-0.5, 0.5]
    float p = 0.0013333558f;
    p = fmaf(p, f, 0.0096181291f);
    p = fmaf(p, f, 0.0555041087f);
    p = fmaf(p, f, 0.2402265069f);
    p = fmaf(p, f, 0.6931471806f);
    p = fmaf(p, f, 1.0f);
    uint32_t sc = ((uint32_t)__float_as_int(kf) - 0x4B3FFF81u) << 23;  // (n+127)<<23
    return p * __int_as_float(sc);
}

#define L2E 1.44269504088896f

// ---------------- init kernels ----------------
__global__ void rope_init_kernel() {
    int idx = blockIdx.x * blockDim.x + threadIdx.x;
    if (idx >= LL * (HD/2)) return;
    int l = idx >> 5;
    int i = idx & 31;
    float inv = (float)pow(10000.0, -(double)(2 * i) / (double)HD);
    float f = (float)l * inv;
    g_cos[idx] = cosf(f);
    g_sin[idx] = sinf(f);
}

// fp32 -> bf16 hi/lo split.  SRC 0: arg `in`; SRC 1: g_att.  DST 0: x; DST 1: w.
template<int SRC, int DST>
__global__ void split_kernel(const float* __restrict__ in, int n4) {
    int i = blockIdx.x * blockDim.x + threadIdx.x;
    if (i >= n4) return;
    const float* src = SRC ? (const float*)g_att : in;
    __nv_bfloat16* hi = DST ? g_whi : g_xhi;
    __nv_bfloat16* lo = DST ? g_wlo : g_xlo;
    float4 vv = ((const float4*)src)[i];
    float f[4] = {vv.x, vv.y, vv.z, vv.w};
    ushort4 ph, pl;
    unsigned short* hp = (unsigned short*)&ph;
    unsigned short* lp = (unsigned short*)&pl;
    #pragma unroll
    for (int j = 0; j < 4; j++) {
        __nv_bfloat16 h = __float2bfloat16(f[j]);
        __nv_bfloat16 l = __float2bfloat16(f[j] - __bfloat162float(h));
        hp[j] = __bfloat16_as_ushort(h);
        lp[j] = __bfloat16_as_ushort(l);
    }
    ((ushort4*)hi)[i] = ph;
    ((ushort4*)lo)[i] = pl;
}

// ---------------- HMMA GEMM ----------------
// C[m,n] = sum_k X[m,k]*W[n,k] + bias[n], bf16-split 3-term mma.sync, fp32 accum.
// MODE 0: fp32 -> outp
// MODE 1: rope+0.125 -> g_qh/g_ql    MODE 2: rope -> g_kh/g_kl    MODE 3: -> g_vh/g_vl
#define LDSTR 40   // smem row stride in halves (32 data + 8 pad)

template<int MODE>
__global__ __launch_bounds__(256, 1) void gemm_mma(const float* __restrict__ bias,
                                                   float* __restrict__ outp) {
    __shared__ __nv_bfloat16 sAh[128*LDSTR];
    __shared__ __nv_bfloat16 sAl[128*LDSTR];
    __shared__ __nv_bfloat16 sBh[128*LDSTR];
    __shared__ __nv_bfloat16 sBl[128*LDSTR];
    __shared__ float bs[128];

    const int tid = threadIdx.x;
    const int wid = tid >> 5;
    const int lid = tid & 31;
    const int n0 = blockIdx.x * 128;
    const int m0 = blockIdx.y * 128;
    const int wm = (wid & 3) * 32;     // warp m offset in tile
    const int wn = (wid >> 2) * 64;    // warp n offset in tile

    if (tid < 128) bs[tid] = bias[n0 + tid];

    const int row_a = tid >> 2;
    const int seg_a = tid & 3;
    const int row_b = (tid + 256) >> 2;
    const int seg_b = (tid + 256) & 3;

    const __nv_bfloat16* Ahi = g_xhi + (size_t)m0 * EE;
    const __nv_bfloat16* Alo = g_xlo + (size_t)m0 * EE;
    const __nv_bfloat16* Bhi = g_whi + (size_t)n0 * EE;
    const __nv_bfloat16* Blo = g_wlo + (size_t)n0 * EE;

    const uint32_t sbAh = smem_u32(sAh), sbAl = smem_u32(sAl);
    const uint32_t sbBh = smem_u32(sBh), sbBl = smem_u32(sBl);
    const int a_row = wm + (lid & 15);
    const int a_koff = (lid >> 4) * 8;
    const int b_row = wn + (lid & 7) + ((lid >> 3) & 1) * 8;
    const int b_koff = (lid >> 4) * 8;

    float acc[2][8][4];
    #pragma unroll
    for (int i = 0; i < 2; i++)
        #pragma unroll
        for (int j = 0; j < 8; j++)
            #pragma unroll
            for (int r = 0; r < 4; r++) acc[i][j][r] = 0.f;

    uint4 pAh0, pAh1, pAl0, pAl1, pBh0, pBh1, pBl0, pBl1;
    {
        const size_t ga0 = (size_t)row_a * EE + seg_a * 8;
        const size_t ga1 = (size_t)row_b * EE + seg_b * 8;
        pAh0 = *(const uint4*)(Ahi + ga0); pAh1 = *(const uint4*)(Ahi + ga1);
        pAl0 = *(const uint4*)(Alo + ga0); pAl1 = *(const uint4*)(Alo + ga1);
        pBh0 = *(const uint4*)(Bhi + ga0); pBh1 = *(const uint4*)(Bhi + ga1);
        pBl0 = *(const uint4*)(Blo + ga0); pBl1 = *(const uint4*)(Blo + ga1);
    }

    for (int kc = 0; kc < EE/32; kc++) {
        __syncthreads();
        {
            const int so0 = row_a * LDSTR + seg_a * 8;
            const int so1 = row_b * LDSTR + seg_b * 8;
            *(uint4*)(sAh + so0) = pAh0; *(uint4*)(sAh + so1) = pAh1;
            *(uint4*)(sAl + so0) = pAl0; *(uint4*)(sAl + so1) = pAl1;
            *(uint4*)(sBh + so0) = pBh0; *(uint4*)(sBh + so1) = pBh1;
            *(uint4*)(sBl + so0) = pBl0; *(uint4*)(sBl + so1) = pBl1;
        }
        __syncthreads();
        if (kc + 1 < EE/32) {
            const int k1 = (kc + 1) * 32;
            const size_t ga0 = (size_t)row_a * EE + k1 + seg_a * 8;
            const size_t ga1 = (size_t)row_b * EE + k1 + seg_b * 8;
            pAh0 = *(const uint4*)(Ahi + ga0); pAh1 = *(const uint4*)(Ahi + ga1);
            pAl0 = *(const uint4*)(Alo + ga0); pAl1 = *(const uint4*)(Alo + ga1);
            pBh0 = *(const uint4*)(Bhi + ga0); pBh1 = *(const uint4*)(Bhi + ga1);
            pBl0 = *(const uint4*)(Blo + ga0); pBl1 = *(const uint4*)(Blo + ga1);
        }

        #pragma unroll
        for (int kk = 0; kk < 32; kk += 16) {
            uint32_t ah[2][4], al[2][4];
            #pragma unroll
            for (int mt = 0; mt < 2; mt++) {
                const uint32_t ao = ((a_row + mt*16) * LDSTR + kk + a_koff) * 2;
                ldsm4(ah[mt][0], ah[mt][1], ah[mt][2], ah[mt][3], sbAh + ao);
                ldsm4(al[mt][0], al[mt][1], al[mt][2], al[mt][3], sbAl + ao);
            }
            uint32_t bh[4][4], bl[4][4];
            #pragma unroll
            for (int nt = 0; nt < 4; nt++) {
                const uint32_t bo = ((b_row + nt*16) * LDSTR + kk + b_koff) * 2;
                ldsm4(bh[nt][0], bh[nt][1], bh[nt][2], bh[nt][3], sbBh + bo);
                ldsm4(bl[nt][0], bl[nt][1], bl[nt][2], bl[nt][3], sbBl + bo);
            }
            #pragma unroll
            for (int mt = 0; mt < 2; mt++)
                #pragma unroll
                for (int nt = 0; nt < 4; nt++) {
                    float* d0 = acc[mt][nt*2];
                    float* d1 = acc[mt][nt*2 + 1];
                    mma_bf16(d0[0], d0[1], d0[2], d0[3],
                             ah[mt][0], ah[mt][1], ah[mt][2], ah[mt][3],
                             bh[nt][0], bh[nt][2]);
                    mma_bf16(d1[0], d1[1], d1[2], d1[3],
                             ah[mt][0], ah[mt][1], ah[mt][2], ah[mt][3],
                             bh[nt][1], bh[nt][3]);
                    mma_bf16(d0[0], d0[1], d0[2], d0[3],
                             al[mt][0], al[mt][1], al[mt][2], al[mt][3],
                             bh[nt][0], bh[nt][2]);
                    mma_bf16(d1[0], d1[1], d1[2], d1[3],
                             al[mt][0], al[mt][1], al[mt][2], al[mt][3],
                             bh[nt][1], bh[nt][3]);
                    mma_bf16(d0[0], d0[1], d0[2], d0[3],
                             ah[mt][0], ah[mt][1], ah[mt][2], ah[mt][3],
                             bl[nt][0], bl[nt][2]);
                    mma_bf16(d1[0], d1[1], d1[2], d1[3],
                             ah[mt][0], ah[mt][1], ah[mt][2], ah[mt][3],
                             bl[nt][1], bl[nt][3]);
                }
        }
    }

    // epilogue
    const int g = lid >> 2;
    const int tig = lid & 3;

    #pragma unroll
    for (int mt = 0; mt < 2; mt++) {
        const int r0 = m0 + wm + mt*16 + g;
        const int r1 = r0 + 8;
        const int l0 = r0 & (LL - 1);
        const int l1 = r1 & (LL - 1);
        #pragma unroll
        for (int nt8 = 0; nt8 < 8; nt8++) {
            const int cl = wn + nt8*8 + tig*2;
            const int c  = n0 + cl;
            float v00 = acc[mt][nt8][0] + bs[cl];
            float v01 = acc[mt][nt8][1] + bs[cl+1];
            float v10 = acc[mt][nt8][2] + bs[cl];
            float v11 = acc[mt][nt8][3] + bs[cl+1];
            if (MODE == 0) {
                *(float2*)(outp + (size_t)r0 * EE + c) = make_float2(v00, v01);
                *(float2*)(outp + (size_t)r1 * EE + c) = make_float2(v10, v11);
            } else {
                if (MODE == 1 || MODE == 2) {
                    const int p = (c & 63) >> 1;
                    float c0 = g_cos[l0*32 + p], s0 = g_sin[l0*32 + p];
                    float c1 = g_cos[l1*32 + p], s1 = g_sin[l1*32 + p];
                    float t00 = v00 * c0 - v01 * s0;
                    float t01 = v01 * c0 + v00 * s0;
                    float t10 = v10 * c1 - v11 * s1;
                    float t11 = v11 * c1 + v10 * s1;
                    if (MODE == 1) { t00 *= 0.125f; t01 *= 0.125f; t10 *= 0.125f; t11 *= 0.125f; }
                    v00 = t00; v01 = t01; v10 = t10; v11 = t11;
                }
                __nv_bfloat16* dh = (MODE == 1) ? g_qh : (MODE == 2) ? g_kh : g_vh;
                __nv_bfloat16* dl = (MODE == 1) ? g_ql : (MODE == 2) ? g_kl : g_vl;
                uint32_t h0 = packbf(v00, v01);
                uint32_t h1 = packbf(v10, v11);
                uint32_t q0p = packbf(v00 - lof(h0), v01 - hif(h0));
                uint32_t q1p = packbf(v10 - lof(h1), v11 - hif(h1));
                *(uint32_t*)(dh + (size_t)r0 * EE + c) = h0;
                *(uint32_t*)(dh + (size_t)r1 * EE + c) = h1;
                *(uint32_t*)(dl + (size_t)r0 * EE + c) = q0p;
                *(uint32_t*)(dl + (size_t)r1 * EE + c) = q1p;
            }
        }
    }
}

// ---------------- HMMA flash attention ----------------
// BQ=128, BK=64, 4 warps (warp = 32 q-rows). 3-term bf16-split for S and PV.
#define ATT_STR 72               // smem row stride in halves
#define AQH 0
#define AQL (128*ATT_STR)        // 9216
#define AKH (2*128*ATT_STR)      // 18432
#define AKL (AKH + 64*ATT_STR)   // 23040
#define AVH (AKL + 64*ATT_STR)   // 27648
#define AVL (AVH + 64*ATT_STR)   // 32256
#define ATT_SMEM ((AVL + 64*ATT_STR) * 2)   // 73728 bytes

__global__ __launch_bounds__(128) void attn_mma() {
    extern __shared__ __nv_bfloat16 ash[];
    const uint32_t sb = smem_u32(ash);
    const int tid = threadIdx.x;
    const int wid = tid >> 5;
    const int lid = tid & 31;
    const int bh = blockIdx.x;
    const int q0 = blockIdx.y * 128;
    const int bi = bh >> 4;
    const int h  = bh & 15;
    const size_t gb = (size_t)bi * LL * EE + h * HD;

    // load Q tile (hi/lo), 128 rows x 64 cols
    #pragma unroll
    for (int it = 0; it < 16; it++) {
        const int arr = it >> 3;                    // 0: qh, 1: ql
        const int rem = (tid + it*128) & 1023;
        const int row = rem >> 3, seg = rem & 7;
        const __nv_bfloat16* src = (arr ? g_ql : g_qh) + gb + (size_t)(q0 + row) * EE + seg * 8;
        *(uint4*)(ash + arr*AQL + row*ATT_STR + seg*8) = *(const uint4*)src;
    }

    float o[2][8][4];
    float m_[4], l_[4];
    #pragma unroll
    for (int mt = 0; mt < 2; mt++)
        #pragma unroll
        for (int j = 0; j < 8; j++)
            #pragma unroll
            for (int r = 0; r < 4; r++) o[mt][j][r] = 0.f;
    #pragma unroll
    for (int s = 0; s < 4; s++) { m_[s] = -1e30f; l_[s] = 0.f; }

    for (int kt = 0; kt < LL; kt += 64) {
        __syncthreads();
        // load K/V tiles (hi/lo), 64 rows x 64 cols each
        #pragma unroll
        for (int it = 0; it < 16; it++) {
            const int arr = it >> 2;                // 0 kh, 1 kl, 2 vh, 3 vl
            const int rem = (tid + it*128) & 511;
            const int row = rem >> 3, seg = rem & 7;
            const __nv_bfloat16* src =
                (arr == 0 ? g_kh : arr == 1 ? g_kl : arr == 2 ? g_vh : g_vl)
                + gb + (size_t)(kt + row) * EE + seg * 8;
            *(uint4*)(ash + AKH + arr*(64*ATT_STR) + row*ATT_STR + seg*8) = *(const uint4*)src;
        }
        __syncthreads();

        // ---- S = Q K^T (3-term) ----
        float s[2][8][4];
        #pragma unroll
        for (int mt = 0; mt < 2; mt++)
            #pragma unroll
            for (int j = 0; j < 8; j++)
                #pragma unroll
                for (int r = 0; r < 4; r++) s[mt][j][r] = 0.f;

        #pragma unroll
        for (int kk = 0; kk < 64; kk += 16) {
            uint32_t aqh[2][4], aql[2][4];
            #pragma unroll
            for (int mt = 0; mt < 2; mt++) {
                const uint32_t ao = sb + ((wid*32 + mt*16 + (lid & 15))*ATT_STR + kk + (lid >> 4)*8) * 2;
                ldsm4(aqh[mt][0], aqh[mt][1], aqh[mt][2], aqh[mt][3], ao);
                ldsm4(aql[mt][0], aql[mt][1], aql[mt][2], aql[mt][3], ao + AQL*2);
            }
            #pragma unroll
            for (int nt = 0; nt < 4; nt++) {
                const uint32_t bo = sb + (AKH + (nt*16 + (lid & 7) + ((lid >> 3) & 1)*8)*ATT_STR
                                          + kk + (lid >> 4)*8) * 2;
                uint32_t kh_[4], kl_[4];
                ldsm4(kh_[0], kh_[1], kh_[2], kh_[3], bo);
                ldsm4(kl_[0], kl_[1], kl_[2], kl_[3], bo + (64*ATT_STR)*2);
                #pragma unroll
                for (int mt = 0; mt < 2; mt++) {
                    float* d0 = s[mt][nt*2];
                    float* d1 = s[mt][nt*2 + 1];
                    mma_bf16(d0[0], d0[1], d0[2], d0[3],
                             aqh[mt][0], aqh[mt][1], aqh[mt][2], aqh[mt][3], kh_[0], kh_[2]);
                    mma_bf16(d1[0], d1[1], d1[2], d1[3],
                             aqh[mt][0], aqh[mt][1], aqh[mt][2], aqh[mt][3], kh_[1], kh_[3]);
                    mma_bf16(d0[0], d0[1], d0[2], d0[3],
                             aql[mt][0], aql[mt][1], aql[mt][2], aql[mt][3], kh_[0], kh_[2]);
                    mma_bf16(d1[0], d1[1], d1[2], d1[3],
                             aql[mt][0], aql[mt][1], aql[mt][2], aql[mt][3], kh_[1], kh_[3]);
                    mma_bf16(d0[0], d0[1], d0[2], d0[3],
                             aqh[mt][0], aqh[mt][1], aqh[mt][2], aqh[mt][3], kl_[0], kl_[2]);
                    mma_bf16(d1[0], d1[1], d1[2], d1[3],
                             aqh[mt][0], aqh[mt][1], aqh[mt][2], aqh[mt][3], kl_[1], kl_[3]);
                }
            }
        }

        // ---- online softmax (poly exp on FMA pipe) ----
        #pragma unroll
        for (int mt = 0; mt < 2; mt++)
            #pragma unroll
            for (int hf = 0; hf < 2; hf++) {
                const int slot = mt*2 + hf;
                float mx = s[mt][0][hf*2];
                #pragma unroll
                for (int j = 0; j < 8; j++) {
                    mx = fmaxf(mx, s[mt][j][hf*2]);
                    mx = fmaxf(mx, s[mt][j][hf*2 + 1]);
                }
                mx = fmaxf(mx, __shfl_xor_sync(0xffffffffu, mx, 1));
                mx = fmaxf(mx, __shfl_xor_sync(0xffffffffu, mx, 2));
                const float mnew = fmaxf(m_[slot], mx);
                const float nl = mnew * L2E;
                const float alpha = exp2p(fmaf(m_[slot], L2E, -nl));
                float rs = 0.f;
                #pragma unroll
                for (int j = 0; j < 8; j++) {
                    float p0 = exp2p(fmaf(s[mt][j][hf*2],     L2E, -nl));
                    float p1 = exp2p(fmaf(s[mt][j][hf*2 + 1], L2E, -nl));
                    s[mt][j][hf*2] = p0;
                    s[mt][j][hf*2 + 1] = p1;
                    rs += p0 + p1;
                }
                rs += __shfl_xor_sync(0xffffffffu, rs, 1);
                rs += __shfl_xor_sync(0xffffffffu, rs, 2);
                l_[slot] = l_[slot] * alpha + rs;
                m_[slot] = mnew;
                #pragma unroll
                for (int j = 0; j < 8; j++) {
                    o[mt][j][hf*2]     *= alpha;
                    o[mt][j][hf*2 + 1] *= alpha;
                }
            }

        // ---- O += P V (3-term; P frags from S regs, V via trans-ldsm) ----
        #pragma unroll
        for (int c = 0; c < 4; c++) {           // key chunks of 16
            uint32_t vh_[4][4], vl_[4][4];
            #pragma unroll
            for (int nt = 0; nt < 4; nt++) {
                const uint32_t vo = sb + (AVH + (c*16 + (lid & 7) + ((lid >> 3) & 1)*8)*ATT_STR
                                          + nt*16 + (lid >> 4)*8) * 2;
                ldsm4t(vh_[nt], vo);
                ldsm4t(vl_[nt], vo + (64*ATT_STR)*2);
            }
            #pragma unroll
            for (int mt = 0; mt < 2; mt++) {
                const float x0 = s[mt][2*c][0], x1 = s[mt][2*c][1];
                const float x2 = s[mt][2*c][2], x3 = s[mt][2*c][3];
                const float y0 = s[mt][2*c+1][0], y1 = s[mt][2*c+1][1];
                const float y2 = s[mt][2*c+1][2], y3 = s[mt][2*c+1][3];
                uint32_t ph[4], pl_[4];
                ph[0] = packbf(x0, x1); ph[1] = packbf(x2, x3);
                ph[2] = packbf(y0, y1); ph[3] = packbf(y2, y3);
                pl_[0] = packbf(x0 - lof(ph[0]), x1 - hif(ph[0]));
                pl_[1] = packbf(x2 - lof(ph[1]), x3 - hif(ph[1]));
                pl_[2] = packbf(y0 - lof(ph[2]), y1 - hif(ph[2]));
                pl_[3] = packbf(y2 - lof(ph[3]), y3 - hif(ph[3]));
                #pragma unroll
                for (int nt = 0; nt < 4; nt++) {
                    float* d0 = o[mt][nt*2];
                    float* d1 = o[mt][nt*2 + 1];
                    mma_bf16(d0[0], d0[1], d0[2], d0[3],
                             ph[0], ph[1], ph[2], ph[3], vh_[nt][0], vh_[nt][1]);
                    mma_bf16(d1[0], d1[1], d1[2], d1[3],
                             ph[0], ph[1], ph[2], ph[3], vh_[nt][2], vh_[nt][3]);
                    mma_bf16(d0[0], d0[1], d0[2], d0[3],
                             pl_[0], pl_[1], pl_[2], pl_[3], vh_[nt][0], vh_[nt][1]);
                    mma_bf16(d1[0], d1[1], d1[2], d1[3],
                             pl_[0], pl_[1], pl_[2], pl_[3], vh_[nt][2], vh_[nt][3]);
                    mma_bf16(d0[0], d0[1], d0[2], d0[3],
                             ph[0], ph[1], ph[2], ph[3], vl_[nt][0], vl_[nt][1]);
                    mma_bf16(d1[0], d1[1], d1[2], d1[3],
                             ph[0], ph[1], ph[2], ph[3], vl_[nt][2], vl_[nt][3]);
                }
            }
        }
    }

    // epilogue: O / l -> g_att
    #pragma unroll
    for (int mt = 0; mt < 2; mt++)
        #pragma unroll
        for (int hf = 0; hf < 2; hf++) {
            const int slot = mt*2 + hf;
            const float inv = 1.f / l_[slot];
            const int row = q0 + wid*32 + mt*16 + (lid >> 2) + hf*8;
            float* dst = g_att + ((size_t)(bi * LL + row)) * EE + h * HD;
            #pragma unroll
            for (int j = 0; j < 8; j++) {
                const int cc = 2*(lid & 3) + 8*j;
                *(float2*)(dst + cc) =
                    make_float2(o[mt][j][hf*2] * inv, o[mt][j][hf*2 + 1] * inv);
            }
        }
}

extern "C" void kernel_launch(void* const* d_in, const int* in_sizes, int n_in,
                              void* d_out, int out_size) {
    const float* x  = (const float*)d_in[0];
    const float* Wq = (const float*)d_in[1];
    const float* bq = (const float*)d_in[2];
    const float* Wk = (const float*)d_in[3];
    const float* bk = (const float*)d_in[4];
    const float* Wv = (const float*)d_in[5];
    const float* bv = (const float*)d_in[6];
    const float* Wo = (const float*)d_in[7];
    const float* bo = (const float*)d_in[8];
    float* out = (float*)d_out;

    rope_init_kernel<<<(LL*32 + 255) / 256, 256>>>();

    const int xn4 = MROWS * EE / 4;
    const int wn4 = EE * EE / 4;
    split_kernel<0,0><<<(xn4 + 255) / 256, 256>>>(x, xn4);

    dim3 gg(EE / 128, MROWS / 128);
    split_kernel<0,1><<<(wn4 + 255) / 256, 256>>>(Wq, wn4);
    gemm_mma<1><<<gg, 256>>>(bq, nullptr);
    split_kernel<0,1><<<(wn4 + 255) / 256, 256>>>(Wk, wn4);
    gemm_mma<2><<<gg, 256>>>(bk, nullptr);
    split_kernel<0,1><<<(wn4 + 255) / 256, 256>>>(Wv, wn4);
    gemm_mma<3><<<gg, 256>>>(bv, nullptr);

    cudaFuncSetAttribute(attn_mma, cudaFuncAttributeMaxDynamicSharedMemorySize, ATT_SMEM);
    attn_mma<<<dim3(BB*HH, LL/128), 128, ATT_SMEM>>>();

    split_kernel<1,0><<<(xn4 + 255) / 256, 256>>>(nullptr, xn4);   // g_att -> xhi/xlo
    split_kernel<0,1><<<(wn4 + 255) / 256, 256>>>(Wo, wn4);
    gemm_mma<0><<<gg, 256>>>(bo, out);
}

// round 12
// speedup vs baseline: 2.3744x; 1.0238x over previous
#include <cuda_runtime.h>
#include <cuda_bf16.h>
#include <math.h>
#include <stdint.h>

#define BB 2
#define LL 2048
#define EE 1024
#define HH 16
#define HD 64
#define MROWS (BB*LL)

// Scratch (device globals; no runtime allocation allowed)
__device__ float g_att[MROWS*EE];     // attention out, [b*l, e]
__device__ float g_cos[LL*(HD/2)];
__device__ float g_sin[LL*(HD/2)];
__device__ __nv_bfloat16 g_xhi[MROWS*EE];
__device__ __nv_bfloat16 g_xlo[MROWS*EE];
__device__ __nv_bfloat16 g_whi[EE*EE];
__device__ __nv_bfloat16 g_wlo[EE*EE];
// rope'd/scaled projections, bf16 hi/lo, [b*l, e]
__device__ __nv_bfloat16 g_qh[MROWS*EE];
__device__ __nv_bfloat16 g_ql[MROWS*EE];
__device__ __nv_bfloat16 g_kh[MROWS*EE];
__device__ __nv_bfloat16 g_kl[MROWS*EE];
__device__ __nv_bfloat16 g_vh[MROWS*EE];
__device__ __nv_bfloat16 g_vl[MROWS*EE];

__device__ __forceinline__ uint32_t smem_u32(const void* p) {
    uint32_t a;
    asm("{ .reg .u64 t; cvta.to.shared.u64 t, %1; cvt.u32.u64 %0, t; }" : "=r"(a) : "l"(p));
    return a;
}

__device__ __forceinline__ void ldsm4(uint32_t& r0, uint32_t& r1, uint32_t& r2, uint32_t& r3,
                                      uint32_t addr) {
    asm volatile("ldmatrix.sync.aligned.m8n8.x4.shared.b16 {%0,%1,%2,%3}, [%4];"
                 : "=r"(r0), "=r"(r1), "=r"(r2), "=r"(r3) : "r"(addr));
}
__device__ __forceinline__ void ldsm4t(uint32_t* r, uint32_t addr) {
    asm volatile("ldmatrix.sync.aligned.m8n8.x4.trans.shared.b16 {%0,%1,%2,%3}, [%4];"
                 : "=r"(r[0]), "=r"(r[1]), "=r"(r[2]), "=r"(r[3]) : "r"(addr));
}

__device__ __forceinline__ void mma_bf16(float& d0, float& d1, float& d2, float& d3,
                                         uint32_t a0, uint32_t a1, uint32_t a2, uint32_t a3,
                                         uint32_t b0, uint32_t b1) {
    asm volatile(
        "mma.sync.aligned.m16n8k16.row.col.f32.bf16.bf16.f32 "
        "{%0,%1,%2,%3}, {%4,%5,%6,%7}, {%8,%9}, {%0,%1,%2,%3};"
        : "+f"(d0), "+f"(d1), "+f"(d2), "+f"(d3)
        : "r"(a0), "r"(a1), "r"(a2), "r"(a3), "r"(b0), "r"(b1));
}

// pack (col c -> lo half, col c+1 -> hi half)
__device__ __forceinline__ uint32_t packbf(float a, float b) {
    uint32_t r;
    asm("cvt.rn.bf16x2.f32 %0, %1, %2;" : "=r"(r) : "f"(b), "f"(a));
    return r;
}
__device__ __forceinline__ float lof(uint32_t u) { return __int_as_float(u << 16); }
__device__ __forceinline__ float hif(uint32_t u) { return __int_as_float(u & 0xFFFF0000u); }

__device__ __forceinline__ void cpa16(uint32_t smem_addr, const void* gptr) {
    asm volatile("cp.async.cg.shared.global [%0], [%1], 16;"
                 :: "r"(smem_addr), "l"(gptr) : "memory");
}

// fast 2^t on the FMA pipe (t <= 0 expected; clamped)
__device__ __forceinline__ float exp2p(float t) {
    t = fmaxf(t, -125.f);
    float kf = t + 12582912.f;        // round to nearest int (RN magic)
    float nf = kf - 12582912.f;
    float f = t - nf;                 // [-0.5, 0.5]
    float p = 0.0013333558f;
    p = fmaf(p, f, 0.0096181291f);
    p = fmaf(p, f, 0.0555041087f);
    p = fmaf(p, f, 0.2402265069f);
    p = fmaf(p, f, 0.6931471806f);
    p = fmaf(p, f, 1.0f);
    uint32_t sc = ((uint32_t)__float_as_int(kf) - 0x4B3FFF81u) << 23;  // (n+127)<<23
    return p * __int_as_float(sc);
}

#define L2E 1.44269504088896f

// ---------------- init kernels ----------------
__global__ void rope_init_kernel() {
    int idx = blockIdx.x * blockDim.x + threadIdx.x;
    if (idx >= LL * (HD/2)) return;
    int l = idx >> 5;
    int i = idx & 31;
    float inv = (float)pow(10000.0, -(double)(2 * i) / (double)HD);
    float f = (float)l * inv;
    g_cos[idx] = cosf(f);
    g_sin[idx] = sinf(f);
}

// fp32 -> bf16 hi/lo split.  SRC 0: arg `in`; SRC 1: g_att.  DST 0: x; DST 1: w.
template<int SRC, int DST>
__global__ void split_kernel(const float* __restrict__ in, int n4) {
    int i = blockIdx.x * blockDim.x + threadIdx.x;
    if (i >= n4) return;
    const float* src = SRC ? (const float*)g_att : in;
    __nv_bfloat16* hi = DST ? g_whi : g_xhi;
    __nv_bfloat16* lo = DST ? g_wlo : g_xlo;
    float4 vv = ((const float4*)src)[i];
    float f[4] = {vv.x, vv.y, vv.z, vv.w};
    ushort4 ph, pl;
    unsigned short* hp = (unsigned short*)&ph;
    unsigned short* lp = (unsigned short*)&pl;
    #pragma unroll
    for (int j = 0; j < 4; j++) {
        __nv_bfloat16 h = __float2bfloat16(f[j]);
        __nv_bfloat16 l = __float2bfloat16(f[j] - __bfloat162float(h));
        hp[j] = __bfloat16_as_ushort(h);
        lp[j] = __bfloat16_as_ushort(l);
    }
    ((ushort4*)hi)[i] = ph;
    ((ushort4*)lo)[i] = pl;
}

// ---------------- HMMA GEMM (cp.async 2-stage pipeline, 2 CTAs/SM) ----------------
// C[m,n] = sum_k X[m,k]*W[n,k] + bias[n], bf16-split 3-term mma.sync, fp32 accum.
// MODE 0: fp32 -> outp
// MODE 1: rope+0.125 -> g_qh/g_ql    MODE 2: rope -> g_kh/g_kl    MODE 3: -> g_vh/g_vl
#define LDSTR 40                       // smem row stride in halves (32 data + 8 pad)
#define ARR_BYTES (128*LDSTR*2)        // 10240 per array
#define STAGE_BYTES (4*ARR_BYTES)      // 40960: [Ah Al Bh Bl]
#define GEMM_SMEM (2*STAGE_BYTES)      // 81920

// one thread's share of a stage fill: 8 cp.async of 16B
__device__ __forceinline__ void gemm_issue(
    uint32_t sbase, int k0,
    const __nv_bfloat16* __restrict__ Ahi, const __nv_bfloat16* __restrict__ Alo,
    const __nv_bfloat16* __restrict__ Bhi, const __nv_bfloat16* __restrict__ Blo,
    int r0, int r1, int s0)
{
    const size_t o0 = (size_t)r0 * EE + k0 + s0 * 8;
    const size_t o1 = (size_t)r1 * EE + k0 + s0 * 8;
    const uint32_t so0 = r0 * (LDSTR*2) + s0 * 16;
    const uint32_t so1 = r1 * (LDSTR*2) + s0 * 16;
    cpa16(sbase               + so0, Ahi + o0);
    cpa16(sbase               + so1, Ahi + o1);
    cpa16(sbase + ARR_BYTES   + so0, Alo + o0);
    cpa16(sbase + ARR_BYTES   + so1, Alo + o1);
    cpa16(sbase + 2*ARR_BYTES + so0, Bhi + o0);
    cpa16(sbase + 2*ARR_BYTES + so1, Bhi + o1);
    cpa16(sbase + 3*ARR_BYTES + so0, Blo + o0);
    cpa16(sbase + 3*ARR_BYTES + so1, Blo + o1);
    asm volatile("cp.async.commit_group;" ::: "memory");
}

template<int MODE>
__global__ __launch_bounds__(256, 2) void gemm_mma(const float* __restrict__ bias,
                                                   float* __restrict__ outp) {
    extern __shared__ char dsm[];
    __shared__ float bs[128];
    const uint32_t sb = smem_u32(dsm);

    const int tid = threadIdx.x;
    const int wid = tid >> 5;
    const int lid = tid & 31;
    const int n0 = blockIdx.x * 128;
    const int m0 = blockIdx.y * 128;
    const int wm = (wid & 3) * 32;     // warp m offset in tile
    const int wn = (wid >> 2) * 64;    // warp n offset in tile

    if (tid < 128) bs[tid] = bias[n0 + tid];

    // copy mapping: 512 16B-segs per array; thread handles segs tid and tid+256
    const int r0c = tid >> 2;
    const int r1c = r0c + 64;
    const int s0c = tid & 3;

    const __nv_bfloat16* Ahi = g_xhi + (size_t)m0 * EE;
    const __nv_bfloat16* Alo = g_xlo + (size_t)m0 * EE;
    const __nv_bfloat16* Bhi = g_whi + (size_t)n0 * EE;
    const __nv_bfloat16* Blo = g_wlo + (size_t)n0 * EE;

    // ldmatrix lane addressing
    const int a_row = wm + (lid & 15);
    const int a_koff = (lid >> 4) * 8;
    const int b_row = wn + (lid & 7) + ((lid >> 3) & 1) * 8;
    const int b_koff = (lid >> 4) * 8;

    float acc[2][8][4];
    #pragma unroll
    for (int i = 0; i < 2; i++)
        #pragma unroll
        for (int j = 0; j < 8; j++)
            #pragma unroll
            for (int r = 0; r < 4; r++) acc[i][j][r] = 0.f;

    // prologue: stage 0 <- chunk 0, stage 1 <- chunk 1
    gemm_issue(sb,               0,  Ahi, Alo, Bhi, Blo, r0c, r1c, s0c);
    gemm_issue(sb + STAGE_BYTES, 32, Ahi, Alo, Bhi, Blo, r0c, r1c, s0c);

    for (int kc = 0; kc < 32; kc++) {
        if (kc < 31) { asm volatile("cp.async.wait_group 1;" ::: "memory"); }
        else         { asm volatile("cp.async.wait_group 0;" ::: "memory"); }
        __syncthreads();

        const uint32_t stb = sb + (kc & 1) * STAGE_BYTES;
        #pragma unroll
        for (int kk = 0; kk < 32; kk += 16) {
            uint32_t ah[2][4], al[2][4];
            #pragma unroll
            for (int mt = 0; mt < 2; mt++) {
                const uint32_t ao = stb + ((a_row + mt*16) * LDSTR + kk + a_koff) * 2;
                ldsm4(ah[mt][0], ah[mt][1], ah[mt][2], ah[mt][3], ao);
                ldsm4(al[mt][0], al[mt][1], al[mt][2], al[mt][3], ao + ARR_BYTES);
            }
            #pragma unroll
            for (int nt = 0; nt < 4; nt++) {
                const uint32_t bo = stb + 2*ARR_BYTES
                                  + ((b_row + nt*16) * LDSTR + kk + b_koff) * 2;
                uint32_t bh[4], bl[4];
                ldsm4(bh[0], bh[1], bh[2], bh[3], bo);
                ldsm4(bl[0], bl[1], bl[2], bl[3], bo + ARR_BYTES);
                #pragma unroll
                for (int mt = 0; mt < 2; mt++) {
                    float* d0 = acc[mt][nt*2];
                    float* d1 = acc[mt][nt*2 + 1];
                    mma_bf16(d0[0], d0[1], d0[2], d0[3],
                             ah[mt][0], ah[mt][1], ah[mt][2], ah[mt][3], bh[0], bh[2]);
                    mma_bf16(d1[0], d1[1], d1[2], d1[3],
                             ah[mt][0], ah[mt][1], ah[mt][2], ah[mt][3], bh[1], bh[3]);
                    mma_bf16(d0[0], d0[1], d0[2], d0[3],
                             al[mt][0], al[mt][1], al[mt][2], al[mt][3], bh[0], bh[2]);
                    mma_bf16(d1[0], d1[1], d1[2], d1[3],
                             al[mt][0], al[mt][1], al[mt][2], al[mt][3], bh[1], bh[3]);
                    mma_bf16(d0[0], d0[1], d0[2], d0[3],
                             ah[mt][0], ah[mt][1], ah[mt][2], ah[mt][3], bl[0], bl[2]);
                    mma_bf16(d1[0], d1[1], d1[2], d1[3],
                             ah[mt][0], ah[mt][1], ah[mt][2], ah[mt][3], bl[1], bl[3]);
                }
            }
        }
        __syncthreads();
        if (kc + 2 < 32) {
            gemm_issue(sb + (kc & 1) * STAGE_BYTES, (kc + 2) * 32,
                       Ahi, Alo, Bhi, Blo, r0c, r1c, s0c);
        }
    }

    // epilogue
    const int g = lid >> 2;
    const int tig = lid & 3;

    #pragma unroll
    for (int mt = 0; mt < 2; mt++) {
        const int r0 = m0 + wm + mt*16 + g;
        const int r1 = r0 + 8;
        const int l0 = r0 & (LL - 1);
        const int l1 = r1 & (LL - 1);
        #pragma unroll
        for (int nt8 = 0; nt8 < 8; nt8++) {
            const int cl = wn + nt8*8 + tig*2;
            const int c  = n0 + cl;
            float v00 = acc[mt][nt8][0] + bs[cl];
            float v01 = acc[mt][nt8][1] + bs[cl+1];
            float v10 = acc[mt][nt8][2] + bs[cl];
            float v11 = acc[mt][nt8][3] + bs[cl+1];
            if (MODE == 0) {
                *(float2*)(outp + (size_t)r0 * EE + c) = make_float2(v00, v01);
                *(float2*)(outp + (size_t)r1 * EE + c) = make_float2(v10, v11);
            } else {
                if (MODE == 1 || MODE == 2) {
                    const int p = (c & 63) >> 1;
                    float c0 = g_cos[l0*32 + p], s0 = g_sin[l0*32 + p];
                    float c1 = g_cos[l1*32 + p], s1 = g_sin[l1*32 + p];
                    float t00 = v00 * c0 - v01 * s0;
                    float t01 = v01 * c0 + v00 * s0;
                    float t10 = v10 * c1 - v11 * s1;
                    float t11 = v11 * c1 + v10 * s1;
                    if (MODE == 1) { t00 *= 0.125f; t01 *= 0.125f; t10 *= 0.125f; t11 *= 0.125f; }
                    v00 = t00; v01 = t01; v10 = t10; v11 = t11;
                }
                __nv_bfloat16* dh = (MODE == 1) ? g_qh : (MODE == 2) ? g_kh : g_vh;
                __nv_bfloat16* dl = (MODE == 1) ? g_ql : (MODE == 2) ? g_kl : g_vl;
                uint32_t h0 = packbf(v00, v01);
                uint32_t h1 = packbf(v10, v11);
                uint32_t q0p = packbf(v00 - lof(h0), v01 - hif(h0));
                uint32_t q1p = packbf(v10 - lof(h1), v11 - hif(h1));
                *(uint32_t*)(dh + (size_t)r0 * EE + c) = h0;
                *(uint32_t*)(dh + (size_t)r1 * EE + c) = h1;
                *(uint32_t*)(dl + (size_t)r0 * EE + c) = q0p;
                *(uint32_t*)(dl + (size_t)r1 * EE + c) = q1p;
            }
        }
    }
}

// ---------------- HMMA flash attention ----------------
// BQ=128, BK=64, 4 warps (warp = 32 q-rows). 3-term bf16-split for S and PV.
#define ATT_STR 72               // smem row stride in halves
#define AQH 0
#define AQL (128*ATT_STR)        // 9216
#define AKH (2*128*ATT_STR)      // 18432
#define AKL (AKH + 64*ATT_STR)   // 23040
#define AVH (AKL + 64*ATT_STR)   // 27648
#define AVL (AVH + 64*ATT_STR)   // 32256
#define ATT_SMEM ((AVL + 64*ATT_STR) * 2)   // 73728 bytes

__global__ __launch_bounds__(128) void attn_mma() {
    extern __shared__ __nv_bfloat16 ash[];
    const uint32_t sb = smem_u32(ash);
    const int tid = threadIdx.x;
    const int wid = tid >> 5;
    const int lid = tid & 31;
    const int bh = blockIdx.x;
    const int q0 = blockIdx.y * 128;
    const int bi = bh >> 4;
    const int h  = bh & 15;
    const size_t gb = (size_t)bi * LL * EE + h * HD;

    // load Q tile (hi/lo), 128 rows x 64 cols
    #pragma unroll
    for (int it = 0; it < 16; it++) {
        const int arr = it >> 3;                    // 0: qh, 1: ql
        const int rem = (tid + it*128) & 1023;
        const int row = rem >> 3, seg = rem & 7;
        const __nv_bfloat16* src = (arr ? g_ql : g_qh) + gb + (size_t)(q0 + row) * EE + seg * 8;
        *(uint4*)(ash + arr*AQL + row*ATT_STR + seg*8) = *(const uint4*)src;
    }

    float o[2][8][4];
    float m_[4], l_[4];
    #pragma unroll
    for (int mt = 0; mt < 2; mt++)
        #pragma unroll
        for (int j = 0; j < 8; j++)
            #pragma unroll
            for (int r = 0; r < 4; r++) o[mt][j][r] = 0.f;
    #pragma unroll
    for (int s = 0; s < 4; s++) { m_[s] = -1e30f; l_[s] = 0.f; }

    for (int kt = 0; kt < LL; kt += 64) {
        __syncthreads();
        // load K/V tiles (hi/lo), 64 rows x 64 cols each
        #pragma unroll
        for (int it = 0; it < 16; it++) {
            const int arr = it >> 2;                // 0 kh, 1 kl, 2 vh, 3 vl
            const int rem = (tid + it*128) & 511;
            const int row = rem >> 3, seg = rem & 7;
            const __nv_bfloat16* src =
                (arr == 0 ? g_kh : arr == 1 ? g_kl : arr == 2 ? g_vh : g_vl)
                + gb + (size_t)(kt + row) * EE + seg * 8;
            *(uint4*)(ash + AKH + arr*(64*ATT_STR) + row*ATT_STR + seg*8) = *(const uint4*)src;
        }
        __syncthreads();

        // ---- S = Q K^T (3-term) ----
        float s[2][8][4];
        #pragma unroll
        for (int mt = 0; mt < 2; mt++)
            #pragma unroll
            for (int j = 0; j < 8; j++)
                #pragma unroll
                for (int r = 0; r < 4; r++) s[mt][j][r] = 0.f;

        #pragma unroll
        for (int kk = 0; kk < 64; kk += 16) {
            uint32_t aqh[2][4], aql[2][4];
            #pragma unroll
            for (int mt = 0; mt < 2; mt++) {
                const uint32_t ao = sb + ((wid*32 + mt*16 + (lid & 15))*ATT_STR + kk + (lid >> 4)*8) * 2;
                ldsm4(aqh[mt][0], aqh[mt][1], aqh[mt][2], aqh[mt][3], ao);
                ldsm4(aql[mt][0], aql[mt][1], aql[mt][2], aql[mt][3], ao + AQL*2);
            }
            #pragma unroll
            for (int nt = 0; nt < 4; nt++) {
                const uint32_t bo = sb + (AKH + (nt*16 + (lid & 7) + ((lid >> 3) & 1)*8)*ATT_STR
                                          + kk + (lid >> 4)*8) * 2;
                uint32_t kh_[4], kl_[4];
                ldsm4(kh_[0], kh_[1], kh_[2], kh_[3], bo);
                ldsm4(kl_[0], kl_[1], kl_[2], kl_[3], bo + (64*ATT_STR)*2);
                #pragma unroll
                for (int mt = 0; mt < 2; mt++) {
                    float* d0 = s[mt][nt*2];
                    float* d1 = s[mt][nt*2 + 1];
                    mma_bf16(d0[0], d0[1], d0[2], d0[3],
                             aqh[mt][0], aqh[mt][1], aqh[mt][2], aqh[mt][3], kh_[0], kh_[2]);
                    mma_bf16(d1[0], d1[1], d1[2], d1[3],
                             aqh[mt][0], aqh[mt][1], aqh[mt][2], aqh[mt][3], kh_[1], kh_[3]);
                    mma_bf16(d0[0], d0[1], d0[2], d0[3],
                             aql[mt][0], aql[mt][1], aql[mt][2], aql[mt][3], kh_[0], kh_[2]);
                    mma_bf16(d1[0], d1[1], d1[2], d1[3],
                             aql[mt][0], aql[mt][1], aql[mt][2], aql[mt][3], kh_[1], kh_[3]);
                    mma_bf16(d0[0], d0[1], d0[2], d0[3],
                             aqh[mt][0], aqh[mt][1], aqh[mt][2], aqh[mt][3], kl_[0], kl_[2]);
                    mma_bf16(d1[0], d1[1], d1[2], d1[3],
                             aqh[mt][0], aqh[mt][1], aqh[mt][2], aqh[mt][3], kl_[1], kl_[3]);
                }
            }
        }

        // ---- online softmax (poly exp on FMA pipe) ----
        #pragma unroll
        for (int mt = 0; mt < 2; mt++)
            #pragma unroll
            for (int hf = 0; hf < 2; hf++) {
                const int slot = mt*2 + hf;
                float mx = s[mt][0][hf*2];
                #pragma unroll
                for (int j = 0; j < 8; j++) {
                    mx = fmaxf(mx, s[mt][j][hf*2]);
                    mx = fmaxf(mx, s[mt][j][hf*2 + 1]);
                }
                mx = fmaxf(mx, __shfl_xor_sync(0xffffffffu, mx, 1));
                mx = fmaxf(mx, __shfl_xor_sync(0xffffffffu, mx, 2));
                const float mnew = fmaxf(m_[slot], mx);
                const float nl = mnew * L2E;
                const float alpha = exp2p(fmaf(m_[slot], L2E, -nl));
                float rs = 0.f;
                #pragma unroll
                for (int j = 0; j < 8; j++) {
                    float p0 = exp2p(fmaf(s[mt][j][hf*2],     L2E, -nl));
                    float p1 = exp2p(fmaf(s[mt][j][hf*2 + 1], L2E, -nl));
                    s[mt][j][hf*2] = p0;
                    s[mt][j][hf*2 + 1] = p1;
                    rs += p0 + p1;
                }
                rs += __shfl_xor_sync(0xffffffffu, rs, 1);
                rs += __shfl_xor_sync(0xffffffffu, rs, 2);
                l_[slot] = l_[slot] * alpha + rs;
                m_[slot] = mnew;
                #pragma unroll
                for (int j = 0; j < 8; j++) {
                    o[mt][j][hf*2]     *= alpha;
                    o[mt][j][hf*2 + 1] *= alpha;
                }
            }

        // ---- O += P V (3-term; P frags from S regs, V via trans-ldsm) ----
        #pragma unroll
        for (int c = 0; c < 4; c++) {           // key chunks of 16
            uint32_t vh_[4][4], vl_[4][4];
            #pragma unroll
            for (int nt = 0; nt < 4; nt++) {
                const uint32_t vo = sb + (AVH + (c*16 + (lid & 7) + ((lid >> 3) & 1)*8)*ATT_STR
                                          + nt*16 + (lid >> 4)*8) * 2;
                ldsm4t(vh_[nt], vo);
                ldsm4t(vl_[nt], vo + (64*ATT_STR)*2);
            }
            #pragma unroll
            for (int mt = 0; mt < 2; mt++) {
                const float x0 = s[mt][2*c][0], x1 = s[mt][2*c][1];
                const float x2 = s[mt][2*c][2], x3 = s[mt][2*c][3];
                const float y0 = s[mt][2*c+1][0], y1 = s[mt][2*c+1][1];
                const float y2 = s[mt][2*c+1][2], y3 = s[mt][2*c+1][3];
                uint32_t ph[4], pl_[4];
                ph[0] = packbf(x0, x1); ph[1] = packbf(x2, x3);
                ph[2] = packbf(y0, y1); ph[3] = packbf(y2, y3);
                pl_[0] = packbf(x0 - lof(ph[0]), x1 - hif(ph[0]));
                pl_[1] = packbf(x2 - lof(ph[1]), x3 - hif(ph[1]));
                pl_[2] = packbf(y0 - lof(ph[2]), y1 - hif(ph[2]));
                pl_[3] = packbf(y2 - lof(ph[3]), y3 - hif(ph[3]));
                #pragma unroll
                for (int nt = 0; nt < 4; nt++) {
                    float* d0 = o[mt][nt*2];
                    float* d1 = o[mt][nt*2 + 1];
                    mma_bf16(d0[0], d0[1], d0[2], d0[3],
                             ph[0], ph[1], ph[2], ph[3], vh_[nt][0], vh_[nt][1]);
                    mma_bf16(d1[0], d1[1], d1[2], d1[3],
                             ph[0], ph[1], ph[2], ph[3], vh_[nt][2], vh_[nt][3]);
                    mma_bf16(d0[0], d0[1], d0[2], d0[3],
                             pl_[0], pl_[1], pl_[2], pl_[3], vh_[nt][0], vh_[nt][1]);
                    mma_bf16(d1[0], d1[1], d1[2], d1[3],
                             pl_[0], pl_[1], pl_[2], pl_[3], vh_[nt][2], vh_[nt][3]);
                    mma_bf16(d0[0], d0[1], d0[2], d0[3],
                             ph[0], ph[1], ph[2], ph[3], vl_[nt][0], vl_[nt][1]);
                    mma_bf16(d1[0], d1[1], d1[2], d1[3],
                             ph[0], ph[1], ph[2], ph[3], vl_[nt][2], vl_[nt][3]);
                }
            }
        }
    }

    // epilogue: O / l -> g_att
    #pragma unroll
    for (int mt = 0; mt < 2; mt++)
        #pragma unroll
        for (int hf = 0; hf < 2; hf++) {
            const int slot = mt*2 + hf;
            const float inv = 1.f / l_[slot];
            const int row = q0 + wid*32 + mt*16 + (lid >> 2) + hf*8;
            float* dst = g_att + ((size_t)(bi * LL + row)) * EE + h * HD;
            #pragma unroll
            for (int j = 0; j < 8; j++) {
                const int cc = 2*(lid & 3) + 8*j;
                *(float2*)(dst + cc) =
                    make_float2(o[mt][j][hf*2] * inv, o[mt][j][hf*2 + 1] * inv);
            }
        }
}

extern "C" void kernel_launch(void* const* d_in, const int* in_sizes, int n_in,
                              void* d_out, int out_size) {
    const float* x  = (const float*)d_in[0];
    const float* Wq = (const float*)d_in[1];
    const float* bq = (const float*)d_in[2];
    const float* Wk = (const float*)d_in[3];
    const float* bk = (const float*)d_in[4];
    const float* Wv = (const float*)d_in[5];
    const float* bv = (const float*)d_in[6];
    const float* Wo = (const float*)d_in[7];
    const float* bo = (const float*)d_in[8];
    float* out = (float*)d_out;

    cudaFuncSetAttribute(gemm_mma<0>, cudaFuncAttributeMaxDynamicSharedMemorySize, GEMM_SMEM);
    cudaFuncSetAttribute(gemm_mma<1>, cudaFuncAttributeMaxDynamicSharedMemorySize, GEMM_SMEM);
    cudaFuncSetAttribute(gemm_mma<2>, cudaFuncAttributeMaxDynamicSharedMemorySize, GEMM_SMEM);
    cudaFuncSetAttribute(gemm_mma<3>, cudaFuncAttributeMaxDynamicSharedMemorySize, GEMM_SMEM);

    rope_init_kernel<<<(LL*32 + 255) / 256, 256>>>();

    const int xn4 = MROWS * EE / 4;
    const int wn4 = EE * EE / 4;
    split_kernel<0,0><<<(xn4 + 255) / 256, 256>>>(x, xn4);

    dim3 gg(EE / 128, MROWS / 128);
    split_kernel<0,1><<<(wn4 + 255) / 256, 256>>>(Wq, wn4);
    gemm_mma<1><<<gg, 256, GEMM_SMEM>>>(bq, nullptr);
    split_kernel<0,1><<<(wn4 + 255) / 256, 256>>>(Wk, wn4);
    gemm_mma<2><<<gg, 256, GEMM_SMEM>>>(bk, nullptr);
    split_kernel<0,1><<<(wn4 + 255) / 256, 256>>>(Wv, wn4);
    gemm_mma<3><<<gg, 256, GEMM_SMEM>>>(bv, nullptr);

    cudaFuncSetAttribute(attn_mma, cudaFuncAttributeMaxDynamicSharedMemorySize, ATT_SMEM);
    attn_mma<<<dim3(BB*HH, LL/128), 128, ATT_SMEM>>>();

    split_kernel<1,0><<<(xn4 + 255) / 256, 256>>>(nullptr, xn4);   // g_att -> xhi/xlo
    split_kernel<0,1><<<(wn4 + 255) / 256, 256>>>(Wo, wn4);
    gemm_mma<0><<<gg, 256, GEMM_SMEM>>>(bo, out);
}